// round 16
// baseline (speedup 1.0000x reference)
#include <cuda_runtime.h>
#include <cuda_bf16.h>
#include <cuda_fp16.h>
#include <cstdint>

#define NN 50000
#define EE 600000
#define DD 128
#define SP 68     // u32 stride for split tiles: conflict-free fragments
#define SCAN_B 1024
#define NBMAX 64

// scratch (no allocation allowed in kernel_launch)
__device__ __half g_h[NN * DD];   // h (raw or dinv-scaled), fp16
__device__ float  g_h1[NN * DD];  // layer-1 output (fp32, feeds gemm2)
__device__ int    g_dege[NN];     // in-degree (edges only)
__device__ float  g_dinv[NN];     // rsqrt(deg+1)
__device__ int    g_rs[NN];       // CSR row start
__device__ int    g_cur[NN];      // binning cursor
__device__ int    g_bsum[NBMAX];  // scan block sums
__device__ int    g_csr[EE];      // CSR column (src) ids

__global__ void k_deg_zero(int n) {
    int i = blockIdx.x * blockDim.x + threadIdx.x;
    if (i < n) g_dege[i] = 0;
}

__global__ void k_deg_count(const int* __restrict__ dst, int e) {
    int i = blockIdx.x * blockDim.x + threadIdx.x;
    if (i < e) {
        int d = dst[i];
        if ((unsigned)d < NN) atomicAdd(&g_dege[d], 1);
    }
}

// block-level exclusive scan of g_dege -> g_rs ; also computes g_dinv (fused)
__global__ void k_scan_blocks(int n) {
    __shared__ int sm[SCAN_B];
    int t = threadIdx.x;
    int i = blockIdx.x * SCAN_B + t;
    int v = (i < n) ? g_dege[i] : 0;
    if (i < n) g_dinv[i] = rsqrtf((float)(v + 1));  // +1 self-loop
    sm[t] = v;
    __syncthreads();
#pragma unroll
    for (int off = 1; off < SCAN_B; off <<= 1) {
        int x = (t >= off) ? sm[t - off] : 0;
        __syncthreads();
        sm[t] += x;
        __syncthreads();
    }
    if (i < n) g_rs[i] = sm[t] - v;           // exclusive within block
    if (t == SCAN_B - 1 && blockIdx.x < NBMAX) g_bsum[blockIdx.x] = sm[t];
}

// adds the cross-block offset; each block redundantly reduces g_bsum[0..bid)
__global__ void k_scan_add(int n, int nb) {
    __shared__ int s_part[2];
    int t = threadIdx.x;
    if (t < 64) {
        int v = (t < (int)blockIdx.x && t < nb) ? g_bsum[t] : 0;
#pragma unroll
        for (int off = 16; off > 0; off >>= 1)
            v += __shfl_down_sync(0xffffffffu, v, off);
        if ((t & 31) == 0) s_part[t >> 5] = v;
    }
    __syncthreads();
    int base = s_part[0] + s_part[1];
    int i = blockIdx.x * SCAN_B + t;
    if (i < n) {
        int r = g_rs[i] + base;
        g_rs[i] = r;
        g_cur[i] = r;
    }
}

// bins edges [off, off+cnt) — two instances run concurrently on both streams
__global__ void k_bin(const int* __restrict__ src, const int* __restrict__ dst,
                      int off, int cnt) {
    int i = off + blockIdx.x * blockDim.x + threadIdx.x;
    if (i < off + cnt) {
        int d = dst[i];
        if ((unsigned)d < NN) {
            int pos = atomicAdd(&g_cur[d], 1);
            if ((unsigned)pos < EE) g_csr[pos] = src[i];
        }
    }
}

// ---- BF16 split helpers -----------------------------------------------------

__device__ __forceinline__ void bsplit(float x, uint16_t& h, uint16_t& l) {
    __nv_bfloat16 hb = __float2bfloat16_rn(x);
    float r = x - __bfloat162float(hb);
    __nv_bfloat16 lb = __float2bfloat16_rn(r);
    h = *reinterpret_cast<uint16_t*>(&hb);
    l = *reinterpret_cast<uint16_t*>(&lb);
}

__device__ __forceinline__ void bsplit2(float a, float b, uint32_t& hi, uint32_t& lo) {
    uint16_t ha, la, hb, lb;
    bsplit(a, ha, la);
    bsplit(b, hb, lb);
    hi = (uint32_t)ha | ((uint32_t)hb << 16);
    lo = (uint32_t)la | ((uint32_t)lb << 16);
}

__device__ __forceinline__ void mma_bf16(float* c, const uint32_t* a, const uint32_t* b) {
    asm("mma.sync.aligned.m16n8k16.row.col.f32.bf16.bf16.f32 "
        "{%0,%1,%2,%3}, {%4,%5,%6,%7}, {%8,%9}, {%0,%1,%2,%3};"
        : "+f"(c[0]), "+f"(c[1]), "+f"(c[2]), "+f"(c[3])
        : "r"(a[0]), "r"(a[1]), "r"(a[2]), "r"(a[3]), "r"(b[0]), "r"(b[1]));
}

// shared gemm core: computes 128x128 tile accumulators from X (fp32) and W
template<int SCALED>
__device__ __forceinline__ void gemm_body(const float* __restrict__ X,
                                          const float* __restrict__ W,
                                          int n, uint32_t* smem) {
    uint32_t* Xh = smem;
    uint32_t* Xl = Xh + DD * SP;
    uint32_t* Wh = Xl + DD * SP;
    uint32_t* Wl = Wh + DD * SP;

    int t = threadIdx.x;
    int row0 = blockIdx.x * 128;

#pragma unroll
    for (int i = 0; i < 16; i++) {
        int idx = i * 256 + t;
        int r  = idx >> 5;
        int c4 = (idx & 31) * 4;
        int k2 = (idx & 31) * 2;
        int grow = row0 + r;
        float4 v = make_float4(0.f, 0.f, 0.f, 0.f);
        if (grow < n) v = *(const float4*)&X[grow * DD + c4];
        uint32_t h0, l0, h1, l1;
        bsplit2(v.x, v.y, h0, l0);
        bsplit2(v.z, v.w, h1, l1);
        Xh[r * SP + k2]     = h0;  Xl[r * SP + k2]     = l0;
        Xh[r * SP + k2 + 1] = h1;  Xl[r * SP + k2 + 1] = l1;
    }
#pragma unroll
    for (int i = 0; i < 32; i++) {
        int p  = i * 256 + t;
        int k2 = p >> 7;
        int nc = p & 127;
        float a = W[(2 * k2) * DD + nc];
        float b = W[(2 * k2 + 1) * DD + nc];
        uint32_t h, l;
        bsplit2(a, b, h, l);
        Wh[nc * SP + k2] = h;
        Wl[nc * SP + k2] = l;
    }
    __syncthreads();

    int lane = t & 31, warp = t >> 5;
    int wm = (warp >> 1) * 32;
    int wn = (warp & 1) * 64;
    int qr = lane >> 2;
    int qc = lane & 3;

    float acc[2][8][4];
#pragma unroll
    for (int i = 0; i < 2; i++)
#pragma unroll
        for (int j = 0; j < 8; j++)
#pragma unroll
            for (int q = 0; q < 4; q++) acc[i][j][q] = 0.f;

#pragma unroll 1
    for (int kc = 0; kc < 8; kc++) {
        int kb = kc * 8 + qc;
        uint32_t ahi[2][4], alo[2][4];
#pragma unroll
        for (int i = 0; i < 2; i++) {
            int ra = (wm + i * 16 + qr) * SP;
            int rb = (wm + i * 16 + qr + 8) * SP;
            ahi[i][0] = Xh[ra + kb];     alo[i][0] = Xl[ra + kb];
            ahi[i][1] = Xh[rb + kb];     alo[i][1] = Xl[rb + kb];
            ahi[i][2] = Xh[ra + kb + 4]; alo[i][2] = Xl[ra + kb + 4];
            ahi[i][3] = Xh[rb + kb + 4]; alo[i][3] = Xl[rb + kb + 4];
        }
#pragma unroll
        for (int j = 0; j < 8; j++) {
            int cb = (wn + j * 8 + qr) * SP;
            uint32_t bhi[2], blo[2];
            bhi[0] = Wh[cb + kb];     blo[0] = Wl[cb + kb];
            bhi[1] = Wh[cb + kb + 4]; blo[1] = Wl[cb + kb + 4];
#pragma unroll
            for (int i = 0; i < 2; i++) {
                mma_bf16(acc[i][j], ahi[i], bhi);
                mma_bf16(acc[i][j], alo[i], bhi);
                mma_bf16(acc[i][j], ahi[i], blo);
            }
        }
    }

    // epilogue
#pragma unroll
    for (int i = 0; i < 2; i++) {
        int ra = row0 + wm + i * 16 + qr;
        int rb = ra + 8;
        float da = 1.f, db = 1.f;
        if (SCALED) {
            da = (ra < n) ? g_dinv[ra] : 0.f;
            db = (rb < n) ? g_dinv[rb] : 0.f;
        }
#pragma unroll
        for (int j = 0; j < 8; j++) {
            int c = wn + j * 8 + 2 * qc;
            if (ra < n) {
                float2 v = {acc[i][j][0] * da, acc[i][j][1] * da};
                *(__half2*)&g_h[ra * DD + c] = __float22half2_rn(v);
            }
            if (rb < n) {
                float2 v = {acc[i][j][2] * db, acc[i][j][3] * db};
                *(__half2*)&g_h[rb * DD + c] = __float22half2_rn(v);
            }
        }
    }
}

__global__ void __launch_bounds__(256)
k_gemm_raw(const float* __restrict__ X, const float* __restrict__ W, int n) {
    extern __shared__ uint32_t smem[];
    gemm_body<0>(X, W, n, smem);
}

__global__ void __launch_bounds__(256)
k_gemm_scaled(const float* __restrict__ W, int n) {
    extern __shared__ uint32_t smem[];
    gemm_body<1>(g_h1, W, n, smem);
}

// 8-deep neighbor-row load helper
#define GLOAD(si, aa, bb)                                        \
    uint2 raw##si = *(const uint2*)&g_h[(si) * DD + fo];         \
    float2 aa = __half22float2(*(__half2*)&raw##si.x);           \
    float2 bb = __half22float2(*(__half2*)&raw##si.y);

// gather over RAW h (layer 1): out[d] = relu( dinv[d]*sum_s h[s]*dinv[s]
//                                             + h[d]*dinv[d]^2 + b )
__global__ void __launch_bounds__(256)
k_gather_raw(const float* __restrict__ b, int n) {
    int w = blockIdx.x * 8 + (threadIdx.x >> 5);
    int lane = threadIdx.x & 31;
    if (w >= n) return;

    int base = g_rs[w];
    int cnt  = g_dege[w];
    float dd = g_dinv[w];
    int fo = lane * 4;

    float4 acc;
    {
        uint2 raw = *(const uint2*)&g_h[w * DD + fo];
        float2 p0 = __half22float2(*(__half2*)&raw.x);
        float2 p1 = __half22float2(*(__half2*)&raw.y);
        acc = make_float4(p0.x * dd, p0.y * dd, p1.x * dd, p1.y * dd);
    }

    for (int j0 = 0; j0 < cnt; j0 += 32) {
        int jj = j0 + lane;
        int   sj = 0;
        float nj = 0.f;
        if (jj < cnt) {
            sj = g_csr[base + jj];
            nj = g_dinv[sj];
        }
        int m = min(32, cnt - j0);
        int j = 0;
        for (; j + 8 <= m; j += 8) {
            int s0 = __shfl_sync(0xffffffffu, sj, j);
            int s1 = __shfl_sync(0xffffffffu, sj, j + 1);
            int s2 = __shfl_sync(0xffffffffu, sj, j + 2);
            int s3 = __shfl_sync(0xffffffffu, sj, j + 3);
            int s4 = __shfl_sync(0xffffffffu, sj, j + 4);
            int s5 = __shfl_sync(0xffffffffu, sj, j + 5);
            int s6 = __shfl_sync(0xffffffffu, sj, j + 6);
            int s7 = __shfl_sync(0xffffffffu, sj, j + 7);
            float n0 = __shfl_sync(0xffffffffu, nj, j);
            float n1 = __shfl_sync(0xffffffffu, nj, j + 1);
            float n2 = __shfl_sync(0xffffffffu, nj, j + 2);
            float n3 = __shfl_sync(0xffffffffu, nj, j + 3);
            float n4 = __shfl_sync(0xffffffffu, nj, j + 4);
            float n5 = __shfl_sync(0xffffffffu, nj, j + 5);
            float n6 = __shfl_sync(0xffffffffu, nj, j + 6);
            float n7 = __shfl_sync(0xffffffffu, nj, j + 7);
            GLOAD(s0, a0, c0) GLOAD(s1, a1, c1) GLOAD(s2, a2, c2) GLOAD(s3, a3, c3)
            GLOAD(s4, a4, c4) GLOAD(s5, a5, c5) GLOAD(s6, a6, c6) GLOAD(s7, a7, c7)
            acc.x += (a0.x*n0 + a1.x*n1) + (a2.x*n2 + a3.x*n3) + (a4.x*n4 + a5.x*n5) + (a6.x*n6 + a7.x*n7);
            acc.y += (a0.y*n0 + a1.y*n1) + (a2.y*n2 + a3.y*n3) + (a4.y*n4 + a5.y*n5) + (a6.y*n6 + a7.y*n7);
            acc.z += (c0.x*n0 + c1.x*n1) + (c2.x*n2 + c3.x*n3) + (c4.x*n4 + c5.x*n5) + (c6.x*n6 + c7.x*n7);
            acc.w += (c0.y*n0 + c1.y*n1) + (c2.y*n2 + c3.y*n3) + (c4.y*n4 + c5.y*n5) + (c6.y*n6 + c7.y*n7);
        }
        for (; j < m; j++) {
            int s = __shfl_sync(0xffffffffu, sj, j);
            float nr = __shfl_sync(0xffffffffu, nj, j);
            GLOAD(s, a0, c0)
            acc.x += a0.x * nr; acc.y += a0.y * nr;
            acc.z += c0.x * nr; acc.w += c0.y * nr;
        }
    }

    float4 bb = *(const float4*)&b[fo];
    float4 r;
    r.x = fmaxf(fmaf(acc.x, dd, bb.x), 0.f);
    r.y = fmaxf(fmaf(acc.y, dd, bb.y), 0.f);
    r.z = fmaxf(fmaf(acc.z, dd, bb.z), 0.f);
    r.w = fmaxf(fmaf(acc.w, dd, bb.w), 0.f);
    *(float4*)&g_h1[w * DD + fo] = r;
}

// gather over PRE-SCALED hs (layer 2): out = relu(dinv[d]*(hs[d]+sum hs[s]) + b)
__global__ void __launch_bounds__(256)
k_gather(const float* __restrict__ b, float* __restrict__ outp, int n) {
    int w = blockIdx.x * 8 + (threadIdx.x >> 5);
    int lane = threadIdx.x & 31;
    if (w >= n) return;

    int base = g_rs[w];
    int cnt  = g_dege[w];
    float dd = g_dinv[w];
    int fo = lane * 4;

    float4 acc;
    {
        uint2 raw = *(const uint2*)&g_h[w * DD + fo];
        float2 p0 = __half22float2(*(__half2*)&raw.x);
        float2 p1 = __half22float2(*(__half2*)&raw.y);
        acc = make_float4(p0.x, p0.y, p1.x, p1.y);
    }

    for (int j0 = 0; j0 < cnt; j0 += 32) {
        int jj = j0 + lane;
        int sj = (jj < cnt) ? g_csr[base + jj] : 0;
        int m = min(32, cnt - j0);
        int j = 0;
        for (; j + 8 <= m; j += 8) {
            int s0 = __shfl_sync(0xffffffffu, sj, j);
            int s1 = __shfl_sync(0xffffffffu, sj, j + 1);
            int s2 = __shfl_sync(0xffffffffu, sj, j + 2);
            int s3 = __shfl_sync(0xffffffffu, sj, j + 3);
            int s4 = __shfl_sync(0xffffffffu, sj, j + 4);
            int s5 = __shfl_sync(0xffffffffu, sj, j + 5);
            int s6 = __shfl_sync(0xffffffffu, sj, j + 6);
            int s7 = __shfl_sync(0xffffffffu, sj, j + 7);
            GLOAD(s0, a0, c0) GLOAD(s1, a1, c1) GLOAD(s2, a2, c2) GLOAD(s3, a3, c3)
            GLOAD(s4, a4, c4) GLOAD(s5, a5, c5) GLOAD(s6, a6, c6) GLOAD(s7, a7, c7)
            acc.x += ((a0.x + a1.x) + (a2.x + a3.x)) + ((a4.x + a5.x) + (a6.x + a7.x));
            acc.y += ((a0.y + a1.y) + (a2.y + a3.y)) + ((a4.y + a5.y) + (a6.y + a7.y));
            acc.z += ((c0.x + c1.x) + (c2.x + c3.x)) + ((c4.x + c5.x) + (c6.x + c7.x));
            acc.w += ((c0.y + c1.y) + (c2.y + c3.y)) + ((c4.y + c5.y) + (c6.y + c7.y));
        }
        for (; j < m; j++) {
            int s = __shfl_sync(0xffffffffu, sj, j);
            GLOAD(s, a0, c0)
            acc.x += a0.x; acc.y += a0.y; acc.z += c0.x; acc.w += c0.y;
        }
    }

    float4 bb = *(const float4*)&b[fo];
    float4 r;
    r.x = fmaxf(fmaf(acc.x, dd, bb.x), 0.f);
    r.y = fmaxf(fmaf(acc.y, dd, bb.y), 0.f);
    r.z = fmaxf(fmaf(acc.z, dd, bb.z), 0.f);
    r.w = fmaxf(fmaf(acc.w, dd, bb.w), 0.f);
    *(float4*)&outp[w * DD + fo] = r;
}

extern "C" void kernel_launch(void* const* d_in, const int* in_sizes, int n_in,
                              void* d_out, int out_size) {
    static cudaStream_t sB = nullptr;
    static cudaEvent_t evF = nullptr, evS = nullptr, evJ = nullptr;
    if (!sB) {   // one-time infra init (first call is outside graph capture)
        cudaStreamCreateWithFlags(&sB, cudaStreamNonBlocking);
        cudaEventCreateWithFlags(&evF, cudaEventDisableTiming);
        cudaEventCreateWithFlags(&evS, cudaEventDisableTiming);
        cudaEventCreateWithFlags(&evJ, cudaEventDisableTiming);
    }

    const float* x  = (const float*)d_in[0];
    const int*   ei = (const int*)d_in[1];
    const float* W1 = (const float*)d_in[2];
    const float* b1 = (const float*)d_in[3];
    const float* W2 = (const float*)d_in[4];
    const float* b2 = (const float*)d_in[5];
    float* out = (float*)d_out;

    int n = in_sizes[0] / DD;       // 50000
    int E = in_sizes[1] / 2;        // 600000
    if (n > NN) n = NN;
    if (E > EE) E = EE;
    const int* srcp = ei;
    const int* dstp = ei + E;

    const int T = 256;
    int gemm_smem = 4 * DD * SP * (int)sizeof(uint32_t);  // 139264 B
    cudaFuncSetAttribute(k_gemm_raw, cudaFuncAttributeMaxDynamicSharedMemorySize, gemm_smem);
    cudaFuncSetAttribute(k_gemm_scaled, cudaFuncAttributeMaxDynamicSharedMemorySize, gemm_smem);

    int gN   = (n + T - 1) / T;
    int gE   = (E + T - 1) / T;
    int gGem = (n + 127) / 128;
    int nb   = (n + SCAN_B - 1) / SCAN_B;   // 49
    int gWarp = (n + 7) / 8;

    int Eh   = E / 2;                       // bin split point
    int gB0  = (Eh + T - 1) / T;
    int gB1  = (E - Eh + T - 1) / T;

    // fork: side stream builds CSR while main stream runs gemm1 (raw h)
    cudaEventRecord(evF, 0);
    cudaStreamWaitEvent(sB, evF, 0);

    k_deg_zero<<<gN, T, 0, sB>>>(n);
    k_deg_count<<<gE, T, 0, sB>>>(dstp, E);
    k_scan_blocks<<<nb, SCAN_B, 0, sB>>>(n);
    k_scan_add<<<nb, SCAN_B, 0, sB>>>(n, nb);
    cudaEventRecord(evS, sB);                           // scan done
    k_bin<<<gB1, T, 0, sB>>>(srcp, dstp, Eh, E - Eh);   // side bins upper half
    cudaEventRecord(evJ, sB);

    k_gemm_raw<<<gGem, T, gemm_smem>>>(x, W1, n);       // independent of CSR
    cudaStreamWaitEvent(0, evS, 0);
    k_bin<<<gB0, T>>>(srcp, dstp, 0, Eh);               // main bins lower half

    // join, then layer-1 aggregation (applies dinv per edge)
    cudaStreamWaitEvent(0, evJ, 0);
    k_gather_raw<<<gWarp, T>>>(b1, n);                  // -> g_h1

    // layer 2: dinv available -> pre-scaled hs path
    k_gemm_scaled<<<gGem, T, gemm_smem>>>(W2, n);       // X = g_h1
    k_gather<<<gWarp, T>>>(b2, out, n);                 // -> d_out
}

// round 17
// speedup vs baseline: 1.0826x; 1.0826x over previous
#include <cuda_runtime.h>
#include <cuda_bf16.h>
#include <cuda_fp16.h>
#include <cstdint>

#define NN 50000
#define EE 600000
#define DD 128
#define SP 68     // u32 stride for split tiles: conflict-free fragments
#define SCAN_B 1024
#define NBMAX 64

// scratch (no allocation allowed in kernel_launch)
// INVARIANT: g_dege == 0 at entry of every kernel_launch run.
//   - first run: CUDA zero-initializes __device__ globals
//   - later runs: k_gather (the last kernel of each run) re-zeroes it
__device__ __half g_h[NN * DD];   // h (raw or dinv-scaled), fp16
__device__ float  g_h1[NN * DD];  // layer-1 output (fp32, feeds gemm2)
__device__ int    g_dege[NN];     // in-degree (edges only)
__device__ float  g_dinv[NN];     // rsqrt(deg+1)
__device__ int    g_rs[NN];       // CSR row start
__device__ int    g_cur[NN];      // binning cursor
__device__ int    g_bsum[NBMAX];  // scan block sums
__device__ int    g_csr[EE];      // CSR column (src) ids

__global__ void k_deg_count(const int* __restrict__ dst, int e) {
    int i = blockIdx.x * blockDim.x + threadIdx.x;
    if (i < e) {
        int d = dst[i];
        if ((unsigned)d < NN) atomicAdd(&g_dege[d], 1);
    }
}

// block-level exclusive scan of g_dege -> g_rs ; also computes g_dinv (fused)
__global__ void k_scan_blocks(int n) {
    __shared__ int sm[SCAN_B];
    int t = threadIdx.x;
    int i = blockIdx.x * SCAN_B + t;
    int v = (i < n) ? g_dege[i] : 0;
    if (i < n) g_dinv[i] = rsqrtf((float)(v + 1));  // +1 self-loop
    sm[t] = v;
    __syncthreads();
#pragma unroll
    for (int off = 1; off < SCAN_B; off <<= 1) {
        int x = (t >= off) ? sm[t - off] : 0;
        __syncthreads();
        sm[t] += x;
        __syncthreads();
    }
    if (i < n) g_rs[i] = sm[t] - v;           // exclusive within block
    if (t == SCAN_B - 1 && blockIdx.x < NBMAX) g_bsum[blockIdx.x] = sm[t];
}

// adds the cross-block offset; each block redundantly reduces g_bsum[0..bid)
__global__ void k_scan_add(int n, int nb) {
    __shared__ int s_part[2];
    int t = threadIdx.x;
    if (t < 64) {
        int v = (t < (int)blockIdx.x && t < nb) ? g_bsum[t] : 0;
#pragma unroll
        for (int off = 16; off > 0; off >>= 1)
            v += __shfl_down_sync(0xffffffffu, v, off);
        if ((t & 31) == 0) s_part[t >> 5] = v;
    }
    __syncthreads();
    int base = s_part[0] + s_part[1];
    int i = blockIdx.x * SCAN_B + t;
    if (i < n) {
        int r = g_rs[i] + base;
        g_rs[i] = r;
        g_cur[i] = r;
    }
}

__global__ void k_bin(const int* __restrict__ src, const int* __restrict__ dst, int e) {
    int i = blockIdx.x * blockDim.x + threadIdx.x;
    if (i < e) {
        int d = dst[i];
        if ((unsigned)d < NN) {
            int pos = atomicAdd(&g_cur[d], 1);
            if ((unsigned)pos < EE) g_csr[pos] = src[i];
        }
    }
}

// ---- BF16 split helpers -----------------------------------------------------

__device__ __forceinline__ void bsplit(float x, uint16_t& h, uint16_t& l) {
    __nv_bfloat16 hb = __float2bfloat16_rn(x);
    float r = x - __bfloat162float(hb);
    __nv_bfloat16 lb = __float2bfloat16_rn(r);
    h = *reinterpret_cast<uint16_t*>(&hb);
    l = *reinterpret_cast<uint16_t*>(&lb);
}

__device__ __forceinline__ void bsplit2(float a, float b, uint32_t& hi, uint32_t& lo) {
    uint16_t ha, la, hb, lb;
    bsplit(a, ha, la);
    bsplit(b, hb, lb);
    hi = (uint32_t)ha | ((uint32_t)hb << 16);
    lo = (uint32_t)la | ((uint32_t)lb << 16);
}

__device__ __forceinline__ void mma_bf16(float* c, const uint32_t* a, const uint32_t* b) {
    asm("mma.sync.aligned.m16n8k16.row.col.f32.bf16.bf16.f32 "
        "{%0,%1,%2,%3}, {%4,%5,%6,%7}, {%8,%9}, {%0,%1,%2,%3};"
        : "+f"(c[0]), "+f"(c[1]), "+f"(c[2]), "+f"(c[3])
        : "r"(a[0]), "r"(a[1]), "r"(a[2]), "r"(a[3]), "r"(b[0]), "r"(b[1]));
}

// shared gemm core: 128x128 output tile, bf16x3 split once at staging
template<int SCALED>
__device__ __forceinline__ void gemm_body(const float* __restrict__ X,
                                          const float* __restrict__ W,
                                          int n, uint32_t* smem) {
    uint32_t* Xh = smem;
    uint32_t* Xl = Xh + DD * SP;
    uint32_t* Wh = Xl + DD * SP;
    uint32_t* Wl = Wh + DD * SP;

    int t = threadIdx.x;
    int row0 = blockIdx.x * 128;

#pragma unroll
    for (int i = 0; i < 16; i++) {
        int idx = i * 256 + t;
        int r  = idx >> 5;
        int c4 = (idx & 31) * 4;
        int k2 = (idx & 31) * 2;
        int grow = row0 + r;
        float4 v = make_float4(0.f, 0.f, 0.f, 0.f);
        if (grow < n) v = *(const float4*)&X[grow * DD + c4];
        uint32_t h0, l0, h1, l1;
        bsplit2(v.x, v.y, h0, l0);
        bsplit2(v.z, v.w, h1, l1);
        Xh[r * SP + k2]     = h0;  Xl[r * SP + k2]     = l0;
        Xh[r * SP + k2 + 1] = h1;  Xl[r * SP + k2 + 1] = l1;
    }
#pragma unroll
    for (int i = 0; i < 32; i++) {
        int p  = i * 256 + t;
        int k2 = p >> 7;
        int nc = p & 127;
        float a = W[(2 * k2) * DD + nc];
        float b = W[(2 * k2 + 1) * DD + nc];
        uint32_t h, l;
        bsplit2(a, b, h, l);
        Wh[nc * SP + k2] = h;
        Wl[nc * SP + k2] = l;
    }
    __syncthreads();

    int lane = t & 31, warp = t >> 5;
    int wm = (warp >> 1) * 32;
    int wn = (warp & 1) * 64;
    int qr = lane >> 2;
    int qc = lane & 3;

    float acc[2][8][4];
#pragma unroll
    for (int i = 0; i < 2; i++)
#pragma unroll
        for (int j = 0; j < 8; j++)
#pragma unroll
            for (int q = 0; q < 4; q++) acc[i][j][q] = 0.f;

#pragma unroll 1
    for (int kc = 0; kc < 8; kc++) {
        int kb = kc * 8 + qc;
        uint32_t ahi[2][4], alo[2][4];
#pragma unroll
        for (int i = 0; i < 2; i++) {
            int ra = (wm + i * 16 + qr) * SP;
            int rb = (wm + i * 16 + qr + 8) * SP;
            ahi[i][0] = Xh[ra + kb];     alo[i][0] = Xl[ra + kb];
            ahi[i][1] = Xh[rb + kb];     alo[i][1] = Xl[rb + kb];
            ahi[i][2] = Xh[ra + kb + 4]; alo[i][2] = Xl[ra + kb + 4];
            ahi[i][3] = Xh[rb + kb + 4]; alo[i][3] = Xl[rb + kb + 4];
        }
#pragma unroll
        for (int j = 0; j < 8; j++) {
            int cb = (wn + j * 8 + qr) * SP;
            uint32_t bhi[2], blo[2];
            bhi[0] = Wh[cb + kb];     blo[0] = Wl[cb + kb];
            bhi[1] = Wh[cb + kb + 4]; blo[1] = Wl[cb + kb + 4];
#pragma unroll
            for (int i = 0; i < 2; i++) {
                mma_bf16(acc[i][j], ahi[i], bhi);
                mma_bf16(acc[i][j], alo[i], bhi);
                mma_bf16(acc[i][j], ahi[i], blo);
            }
        }
    }

    // epilogue (optionally scaled by dinv[row]), store fp16
#pragma unroll
    for (int i = 0; i < 2; i++) {
        int ra = row0 + wm + i * 16 + qr;
        int rb = ra + 8;
        float da = 1.f, db = 1.f;
        if (SCALED) {
            da = (ra < n) ? g_dinv[ra] : 0.f;
            db = (rb < n) ? g_dinv[rb] : 0.f;
        }
#pragma unroll
        for (int j = 0; j < 8; j++) {
            int c = wn + j * 8 + 2 * qc;
            if (ra < n) {
                float2 v = {acc[i][j][0] * da, acc[i][j][1] * da};
                *(__half2*)&g_h[ra * DD + c] = __float22half2_rn(v);
            }
            if (rb < n) {
                float2 v = {acc[i][j][2] * db, acc[i][j][3] * db};
                *(__half2*)&g_h[rb * DD + c] = __float22half2_rn(v);
            }
        }
    }
}

__global__ void __launch_bounds__(256)
k_gemm_raw(const float* __restrict__ X, const float* __restrict__ W, int n) {
    extern __shared__ uint32_t smem[];
    gemm_body<0>(X, W, n, smem);
}

__global__ void __launch_bounds__(256)
k_gemm_scaled(const float* __restrict__ W, int n) {
    extern __shared__ uint32_t smem[];
    gemm_body<1>(g_h1, W, n, smem);
}

// gather over RAW h (layer 1): out[d] = relu( dinv[d]*sum_s h[s]*dinv[s]
//                                             + h[d]*dinv[d]^2 + b )
__global__ void __launch_bounds__(256)
k_gather_raw(const float* __restrict__ b, int n) {
    int w = blockIdx.x * 8 + (threadIdx.x >> 5);
    int lane = threadIdx.x & 31;
    if (w >= n) return;

    int base = g_rs[w];
    int cnt  = g_dege[w];
    float dd = g_dinv[w];
    int fo = lane * 4;

    float4 acc;
    {
        uint2 raw = *(const uint2*)&g_h[w * DD + fo];
        float2 p0 = __half22float2(*(__half2*)&raw.x);
        float2 p1 = __half22float2(*(__half2*)&raw.y);
        acc = make_float4(p0.x * dd, p0.y * dd, p1.x * dd, p1.y * dd);
    }

    for (int j0 = 0; j0 < cnt; j0 += 32) {
        int jj = j0 + lane;
        int   sj = 0;
        float nj = 0.f;
        if (jj < cnt) {
            sj = g_csr[base + jj];
            nj = g_dinv[sj];
        }
        int m = min(32, cnt - j0);
        int j = 0;
        for (; j + 4 <= m; j += 4) {
            int s0 = __shfl_sync(0xffffffffu, sj, j);
            int s1 = __shfl_sync(0xffffffffu, sj, j + 1);
            int s2 = __shfl_sync(0xffffffffu, sj, j + 2);
            int s3 = __shfl_sync(0xffffffffu, sj, j + 3);
            float n0 = __shfl_sync(0xffffffffu, nj, j);
            float n1 = __shfl_sync(0xffffffffu, nj, j + 1);
            float n2 = __shfl_sync(0xffffffffu, nj, j + 2);
            float n3 = __shfl_sync(0xffffffffu, nj, j + 3);
            uint2 r0 = *(const uint2*)&g_h[s0 * DD + fo];
            uint2 r1 = *(const uint2*)&g_h[s1 * DD + fo];
            uint2 r2 = *(const uint2*)&g_h[s2 * DD + fo];
            uint2 r3 = *(const uint2*)&g_h[s3 * DD + fo];
            float2 a0 = __half22float2(*(__half2*)&r0.x), c0 = __half22float2(*(__half2*)&r0.y);
            float2 a1 = __half22float2(*(__half2*)&r1.x), c1 = __half22float2(*(__half2*)&r1.y);
            float2 a2 = __half22float2(*(__half2*)&r2.x), c2 = __half22float2(*(__half2*)&r2.y);
            float2 a3 = __half22float2(*(__half2*)&r3.x), c3 = __half22float2(*(__half2*)&r3.y);
            acc.x += (a0.x * n0 + a1.x * n1) + (a2.x * n2 + a3.x * n3);
            acc.y += (a0.y * n0 + a1.y * n1) + (a2.y * n2 + a3.y * n3);
            acc.z += (c0.x * n0 + c1.x * n1) + (c2.x * n2 + c3.x * n3);
            acc.w += (c0.y * n0 + c1.y * n1) + (c2.y * n2 + c3.y * n3);
        }
        for (; j < m; j++) {
            int s = __shfl_sync(0xffffffffu, sj, j);
            float nr = __shfl_sync(0xffffffffu, nj, j);
            uint2 r0 = *(const uint2*)&g_h[s * DD + fo];
            float2 a0 = __half22float2(*(__half2*)&r0.x);
            float2 c0 = __half22float2(*(__half2*)&r0.y);
            acc.x += a0.x * nr; acc.y += a0.y * nr;
            acc.z += c0.x * nr; acc.w += c0.y * nr;
        }
    }

    float4 bb = *(const float4*)&b[fo];
    float4 r;
    r.x = fmaxf(fmaf(acc.x, dd, bb.x), 0.f);
    r.y = fmaxf(fmaf(acc.y, dd, bb.y), 0.f);
    r.z = fmaxf(fmaf(acc.z, dd, bb.z), 0.f);
    r.w = fmaxf(fmaf(acc.w, dd, bb.w), 0.f);
    *(float4*)&g_h1[w * DD + fo] = r;
}

// gather over PRE-SCALED hs (layer 2): out = relu(dinv[d]*(hs[d]+sum hs[s]) + b)
// ALSO restores the g_dege==0 invariant for the next run.
__global__ void __launch_bounds__(256)
k_gather(const float* __restrict__ b, float* __restrict__ outp, int n) {
    int w = blockIdx.x * 8 + (threadIdx.x >> 5);
    int lane = threadIdx.x & 31;
    if (w >= n) return;

    int base = g_rs[w];
    int cnt  = g_dege[w];
    float dd = g_dinv[w];
    int fo = lane * 4;
    if (lane == 0) g_dege[w] = 0;   // restore invariant for next replay

    float4 acc;
    {
        uint2 raw = *(const uint2*)&g_h[w * DD + fo];
        float2 p0 = __half22float2(*(__half2*)&raw.x);
        float2 p1 = __half22float2(*(__half2*)&raw.y);
        acc = make_float4(p0.x, p0.y, p1.x, p1.y);
    }

    for (int j0 = 0; j0 < cnt; j0 += 32) {
        int jj = j0 + lane;
        int sj = (jj < cnt) ? g_csr[base + jj] : 0;
        int m = min(32, cnt - j0);
        int j = 0;
        for (; j + 4 <= m; j += 4) {
            int s0 = __shfl_sync(0xffffffffu, sj, j);
            int s1 = __shfl_sync(0xffffffffu, sj, j + 1);
            int s2 = __shfl_sync(0xffffffffu, sj, j + 2);
            int s3 = __shfl_sync(0xffffffffu, sj, j + 3);
            uint2 r0 = *(const uint2*)&g_h[s0 * DD + fo];
            uint2 r1 = *(const uint2*)&g_h[s1 * DD + fo];
            uint2 r2 = *(const uint2*)&g_h[s2 * DD + fo];
            uint2 r3 = *(const uint2*)&g_h[s3 * DD + fo];
            float2 a0 = __half22float2(*(__half2*)&r0.x), b0 = __half22float2(*(__half2*)&r0.y);
            float2 a1 = __half22float2(*(__half2*)&r1.x), b1 = __half22float2(*(__half2*)&r1.y);
            float2 a2 = __half22float2(*(__half2*)&r2.x), b2 = __half22float2(*(__half2*)&r2.y);
            float2 a3 = __half22float2(*(__half2*)&r3.x), b3 = __half22float2(*(__half2*)&r3.y);
            acc.x += (a0.x + a1.x) + (a2.x + a3.x);
            acc.y += (a0.y + a1.y) + (a2.y + a3.y);
            acc.z += (b0.x + b1.x) + (b2.x + b3.x);
            acc.w += (b0.y + b1.y) + (b2.y + b3.y);
        }
        for (; j < m; j++) {
            int s = __shfl_sync(0xffffffffu, sj, j);
            uint2 r0 = *(const uint2*)&g_h[s * DD + fo];
            float2 a0 = __half22float2(*(__half2*)&r0.x);
            float2 b0 = __half22float2(*(__half2*)&r0.y);
            acc.x += a0.x; acc.y += a0.y; acc.z += b0.x; acc.w += b0.y;
        }
    }

    float4 bb = *(const float4*)&b[fo];
    float4 r;
    r.x = fmaxf(fmaf(acc.x, dd, bb.x), 0.f);
    r.y = fmaxf(fmaf(acc.y, dd, bb.y), 0.f);
    r.z = fmaxf(fmaf(acc.z, dd, bb.z), 0.f);
    r.w = fmaxf(fmaf(acc.w, dd, bb.w), 0.f);
    *(float4*)&outp[w * DD + fo] = r;
}

extern "C" void kernel_launch(void* const* d_in, const int* in_sizes, int n_in,
                              void* d_out, int out_size) {
    static cudaStream_t sB = nullptr;
    static cudaEvent_t evF = nullptr, evJ = nullptr;
    if (!sB) {   // one-time infra init (first call is outside graph capture)
        cudaStreamCreateWithFlags(&sB, cudaStreamNonBlocking);
        cudaEventCreateWithFlags(&evF, cudaEventDisableTiming);
        cudaEventCreateWithFlags(&evJ, cudaEventDisableTiming);
    }

    const float* x  = (const float*)d_in[0];
    const int*   ei = (const int*)d_in[1];
    const float* W1 = (const float*)d_in[2];
    const float* b1 = (const float*)d_in[3];
    const float* W2 = (const float*)d_in[4];
    const float* b2 = (const float*)d_in[5];
    float* out = (float*)d_out;

    int n = in_sizes[0] / DD;       // 50000
    int E = in_sizes[1] / 2;        // 600000
    if (n > NN) n = NN;
    if (E > EE) E = EE;
    const int* srcp = ei;
    const int* dstp = ei + E;

    const int T = 256;
    int gemm_smem = 4 * DD * SP * (int)sizeof(uint32_t);  // 139264 B
    cudaFuncSetAttribute(k_gemm_raw, cudaFuncAttributeMaxDynamicSharedMemorySize, gemm_smem);
    cudaFuncSetAttribute(k_gemm_scaled, cudaFuncAttributeMaxDynamicSharedMemorySize, gemm_smem);

    int gE   = (E + T - 1) / T;
    int gGem = (n + 127) / 128;
    int nb   = (n + SCAN_B - 1) / SCAN_B;   // 49
    int gWarp = (n + 7) / 8;

    // fork: side stream builds CSR while main stream runs gemm1 (raw h)
    // (g_dege is already zero: zero-init on first call, restored by k_gather after)
    cudaEventRecord(evF, 0);
    cudaStreamWaitEvent(sB, evF, 0);

    k_deg_count<<<gE, T, 0, sB>>>(dstp, E);
    k_scan_blocks<<<nb, SCAN_B, 0, sB>>>(n);
    k_scan_add<<<nb, SCAN_B, 0, sB>>>(n, nb);
    k_bin<<<gE, T, 0, sB>>>(srcp, dstp, E);
    cudaEventRecord(evJ, sB);

    k_gemm_raw<<<gGem, T, gemm_smem>>>(x, W1, n);       // independent of CSR

    // join, then layer-1 aggregation (applies dinv per edge)
    cudaStreamWaitEvent(0, evJ, 0);
    k_gather_raw<<<gWarp, T>>>(b1, n);                  // -> g_h1

    // layer 2: dinv available -> pre-scaled hs path
    k_gemm_scaled<<<gGem, T, gemm_smem>>>(W2, n);       // X = g_h1
    k_gather<<<gWarp, T>>>(b2, out, n);                 // -> d_out (+ deg reset)
}